// round 13
// baseline (speedup 1.0000x reference)
#include <cuda_runtime.h>
#include <cuda_fp16.h>

#define GSZ 64
#define NTILE (GSZ * GSZ * GSZ)   // 262144 tiles
#define NSLAB (GSZ * GSZ)         // 4096 prep slabs (z, y0)

// All-origins tile buffer: tile (z, y0, x0) holds the 4x4 (y,x) patch of
// cells (z, y0..y0+3, x0..x0+3), 4 channels, fp16 -> 16 cells * 8B = 128B
// = one cache line. 32 MB (L2-resident).
// uint4 j (j=0..7) holds cells 2j, 2j+1 (cell index c = dy*4+dx).
// Cell = {half2(ch0,ch1), half2(ch2,ch3)}.
__device__ uint4 g_tiles[NTILE * 8];

// Device-wide barrier state (reset by last departing block each run).
__device__ unsigned g_arrive = 0;
__device__ unsigned g_depart = 0;

// ---------------------------------------------------------------------------
#define LDG256(r, ptr)                                                        \
    asm("ld.global.nc.v8.b32 {%0,%1,%2,%3,%4,%5,%6,%7}, [%8];"                \
        : "=r"(r##0), "=r"(r##1), "=r"(r##2), "=r"(r##3),                     \
          "=r"(r##4), "=r"(r##5), "=r"(r##6), "=r"(r##7)                      \
        : "l"(ptr))

#define CONSUME(r, wz)                                                        \
    do {                                                                      \
        __half2 d01 = __hmul2(hx0, *reinterpret_cast<__half2*>(&r##0));       \
        d01 = __hfma2(hx1, *reinterpret_cast<__half2*>(&r##2), d01);          \
        d01 = __hfma2(hx2, *reinterpret_cast<__half2*>(&r##4), d01);          \
        d01 = __hfma2(hx3, *reinterpret_cast<__half2*>(&r##6), d01);          \
        __half2 d23 = __hmul2(hx0, *reinterpret_cast<__half2*>(&r##1));       \
        d23 = __hfma2(hx1, *reinterpret_cast<__half2*>(&r##3), d23);          \
        d23 = __hfma2(hx2, *reinterpret_cast<__half2*>(&r##5), d23);          \
        d23 = __hfma2(hx3, *reinterpret_cast<__half2*>(&r##7), d23);          \
        float2 f01 = __half22float2(d01);                                     \
        float2 f23 = __half22float2(d23);                                     \
        a0 = fmaf(wz, f01.x, a0);                                             \
        a1 = fmaf(wz, f01.y, a1);                                             \
        a2 = fmaf(wz, f23.x, a2);                                             \
        a3 = fmaf(wz, f23.y, a3);                                             \
    } while (0)

// ---------------------------------------------------------------------------
// Fused persistent kernel.
//  Phase 1 (prep): grid-stride over 4096 (z,y0) slabs. Each block loads the
//    4 source rows once (coalesced), converts to fp16 once, writes the 64
//    tiles of the slab as 512 coalesced uint4 stores. Bit-identical contents
//    to the previous two-kernel prep.
//  Barrier: one atomic arrival per block; thread 0 spins, block syncs.
//  Phase 2 (main): grid-stride quad mapping, identical math to best kernel:
//    lane lx owns y-row dy=lx; one LDG.256 per z covers the whole 128B tile
//    line per warp instruction (4 L1 wavefronts per point); depth-2 z pipe.
//  Reset: last departing block zeroes the barrier counters for next replay.
// ---------------------------------------------------------------------------
__global__ void __launch_bounds__(256) k_fused(const float* __restrict__ knots,
                                               const float* __restrict__ coords,
                                               float* __restrict__ out,
                                               int n, int nblocks)
{
    __shared__ uint2 srow[4][GSZ + 1];   // [dy][x] cell (2x half2), +1 pad

    // ---------------- Phase 1: prep ----------------
    for (int slab = blockIdx.x; slab < NSLAB; slab += nblocks) {
        int z  = slab >> 6;
        int y0 = slab & 63;
        int t  = threadIdx.x;
        {
            int dy = t >> 6;
            int x  = t & 63;
            int yr = min(y0, GSZ - 4) + dy;
            float4 k = __ldg(reinterpret_cast<const float4*>(knots)
                             + (z * GSZ + yr) * GSZ + x);
            __half2 h0 = __floats2half2_rn(k.x, k.y);
            __half2 h1 = __floats2half2_rn(k.z, k.w);
            uint2 cell;
            cell.x = *reinterpret_cast<unsigned*>(&h0);
            cell.y = *reinterpret_cast<unsigned*>(&h1);
            srow[dy][x] = cell;
        }
        __syncthreads();

        size_t base = (size_t)((z * GSZ + y0) * GSZ) * 8;
#pragma unroll
        for (int r = 0; r < 2; r++) {
            int o   = t + r * 256;
            int x0  = o >> 3;
            int j   = o & 7;
            int dyo = j >> 1;
            int q   = j & 1;
            int xr  = min(x0, GSZ - 4) + 2 * q;
            uint2 c0 = srow[dyo][xr];
            uint2 c1 = srow[dyo][xr + 1];
            g_tiles[base + o] = make_uint4(c0.x, c0.y, c1.x, c1.y);
        }
        __syncthreads();   // srow reused next slab
    }

    // ---------------- Barrier ----------------
    __threadfence();                  // publish tile writes (L2)
    __syncthreads();
    if (threadIdx.x == 0) {
        atomicAdd(&g_arrive, 1u);
        while (*((volatile unsigned*)&g_arrive) < (unsigned)nblocks) {
            __nanosleep(64);
        }
    }
    __syncthreads();
    __threadfence();                  // acquire ordering for tile reads

    // ---------------- Phase 2: main ----------------
    long long total = 4LL * n;
    long long stride = (long long)nblocks * 256;
    for (long long tid = (long long)blockIdx.x * 256 + threadIdx.x;
         tid < total; tid += stride) {
        int p  = (int)(tid >> 2);
        int lx = (int)(tid & 3);

        float zc = __ldg(&coords[p * 3 + 0]);
        float yc = __ldg(&coords[p * 3 + 1]);
        float xc = __ldg(&coords[p * 3 + 2]);

        float fz = floorf(zc), fy = floorf(yc), fx = floorf(xc);
        int iz = (int)fz, iy = (int)fy, ix = (int)fx;
        float sz = zc - fz, sy = yc - fy, sx = xc - fx;
        iz = min(max(iz, 1), GSZ - 3);
        iy = min(max(iy, 1), GSZ - 3);
        ix = min(max(ix, 1), GSZ - 3);

        const uint4* tbase = g_tiles
            + (size_t)(((iz - 1) * GSZ + (iy - 1)) * GSZ + (ix - 1)) * 8 + lx * 2;
        const size_t zstep = (size_t)(GSZ * GSZ * 8);

        unsigned A0, A1, A2, A3, A4, A5, A6, A7;
        unsigned B0, B1, B2, B3, B4, B5, B6, B7;
        LDG256(A, reinterpret_cast<const unsigned*>(tbase));
        LDG256(B, reinterpret_cast<const unsigned*>(tbase + zstep));

        float cz0 = sz * (-0.5f + sz * (1.0f - 0.5f * sz));
        float cz1 = 1.0f + sz * sz * (-2.5f + 1.5f * sz);
        float cz2 = sz * (0.5f + sz * (2.0f - 1.5f * sz));
        float cz3 = sz * sz * (0.5f * sz - 0.5f);

        float cyl;
        {
            float c0 = sy * (-0.5f + sy * (1.0f - 0.5f * sy));
            float c1 = 1.0f + sy * sy * (-2.5f + 1.5f * sy);
            float c2 = sy * (0.5f + sy * (2.0f - 1.5f * sy));
            float c3 = sy * sy * (0.5f * sy - 0.5f);
            float ca = (lx & 1) ? c1 : c0;
            float cb = (lx & 1) ? c3 : c2;
            cyl = (lx & 2) ? cb : ca;
        }

        __half2 hx0, hx1, hx2, hx3;
        {
            float c0 = sx * (-0.5f + sx * (1.0f - 0.5f * sx));
            float c1 = 1.0f + sx * sx * (-2.5f + 1.5f * sx);
            float c2 = sx * (0.5f + sx * (2.0f - 1.5f * sx));
            float c3 = sx * sx * (0.5f * sx - 0.5f);
            hx0 = __float2half2_rn(c0);
            hx1 = __float2half2_rn(c1);
            hx2 = __float2half2_rn(c2);
            hx3 = __float2half2_rn(c3);
        }

        float a0 = 0.f, a1 = 0.f, a2 = 0.f, a3 = 0.f;

        CONSUME(A, cz0 * cyl);
        LDG256(A, reinterpret_cast<const unsigned*>(tbase + 2 * zstep));
        CONSUME(B, cz1 * cyl);
        LDG256(B, reinterpret_cast<const unsigned*>(tbase + 3 * zstep));
        CONSUME(A, cz2 * cyl);
        CONSUME(B, cz3 * cyl);

#pragma unroll
        for (int d = 1; d < 4; d <<= 1) {
            a0 += __shfl_xor_sync(0xffffffffu, a0, d);
            a1 += __shfl_xor_sync(0xffffffffu, a1, d);
            a2 += __shfl_xor_sync(0xffffffffu, a2, d);
            a3 += __shfl_xor_sync(0xffffffffu, a3, d);
        }

        if (lx == 0)
            reinterpret_cast<float4*>(out)[p] = make_float4(a0, a1, a2, a3);
    }

    // ---------------- Reset for next replay ----------------
    __syncthreads();
    if (threadIdx.x == 0) {
        unsigned d = atomicAdd(&g_depart, 1u);
        if (d == (unsigned)(nblocks - 1)) {
            g_arrive = 0;
            g_depart = 0;
            __threadfence();
        }
    }
}

// ---------------------------------------------------------------------------
extern "C" void kernel_launch(void* const* d_in, const int* in_sizes, int n_in,
                              void* d_out, int out_size) {
    const float* coords = (const float*)d_in[0];  // [N,3] f32
    const float* knots  = (const float*)d_in[1];  // [64,64,64,4] f32
    float* out          = (float*)d_out;          // [N,4] f32

    int n = in_sizes[0] / 3;

    // Grid = exactly resident capacity (deadlock-safe for the spin barrier).
    int dev = 0, nsm = 0, per_sm = 0;
    cudaGetDevice(&dev);
    cudaDeviceGetAttribute(&nsm, cudaDevAttrMultiProcessorCount, dev);
    cudaError_t e = cudaOccupancyMaxActiveBlocksPerMultiprocessor(
        &per_sm, k_fused, 256, 0);
    if (e != cudaSuccess || per_sm < 1) per_sm = 1;   // conservative fallback
    if (nsm < 1) nsm = 1;
    int nblocks = nsm * per_sm;

    k_fused<<<nblocks, 256>>>(knots, coords, out, n, nblocks);
}

// round 14
// speedup vs baseline: 1.0356x; 1.0356x over previous
#include <cuda_runtime.h>
#include <cuda_fp16.h>

#define GSZ 64
#define NTILE (GSZ * GSZ * GSZ)   // 262144 tiles
#define NSLAB (GSZ * GSZ)         // 4096 prep slabs (z, y0)

// All-origins tile buffer: tile (z, y0, x0) holds the 4x4 (y,x) patch of
// cells (z, y0..y0+3, x0..x0+3), 4 channels, fp16 -> 16 cells * 8B = 128B
// = one cache line. 32 MB (L2-resident).
// uint4 j (j=0..7) holds cells 2j, 2j+1 (cell index c = dy*4+dx).
// Cell = {half2(ch0,ch1), half2(ch2,ch3)}.
__device__ uint4 g_tiles[NTILE * 8];

// Device-wide barrier state (reset by last departing block each run).
__device__ unsigned g_arrive = 0;
__device__ unsigned g_depart = 0;

// ---------------------------------------------------------------------------
#define LDG256(r, ptr)                                                        \
    asm("ld.global.nc.v8.b32 {%0,%1,%2,%3,%4,%5,%6,%7}, [%8];"                \
        : "=r"(r##0), "=r"(r##1), "=r"(r##2), "=r"(r##3),                     \
          "=r"(r##4), "=r"(r##5), "=r"(r##6), "=r"(r##7)                      \
        : "l"(ptr))

#define CONSUME(r, wz)                                                        \
    do {                                                                      \
        __half2 d01 = __hmul2(hx0, *reinterpret_cast<__half2*>(&r##0));       \
        d01 = __hfma2(hx1, *reinterpret_cast<__half2*>(&r##2), d01);          \
        d01 = __hfma2(hx2, *reinterpret_cast<__half2*>(&r##4), d01);          \
        d01 = __hfma2(hx3, *reinterpret_cast<__half2*>(&r##6), d01);          \
        __half2 d23 = __hmul2(hx0, *reinterpret_cast<__half2*>(&r##1));       \
        d23 = __hfma2(hx1, *reinterpret_cast<__half2*>(&r##3), d23);          \
        d23 = __hfma2(hx2, *reinterpret_cast<__half2*>(&r##5), d23);          \
        d23 = __hfma2(hx3, *reinterpret_cast<__half2*>(&r##7), d23);          \
        float2 f01 = __half22float2(d01);                                     \
        float2 f23 = __half22float2(d23);                                     \
        a0 = fmaf(wz, f01.x, a0);                                             \
        a1 = fmaf(wz, f01.y, a1);                                             \
        a2 = fmaf(wz, f23.x, a2);                                             \
        a3 = fmaf(wz, f23.y, a3);                                             \
    } while (0)

// ---------------------------------------------------------------------------
// Fused persistent kernel.
//  Phase 1 (prep): grid-stride over 4096 (z,y0) slabs. Each block loads the
//    4 source rows once (coalesced), converts to fp16 once, writes the 64
//    tiles of the slab as 512 coalesced uint4 stores. Bit-identical contents
//    to the previous two-kernel prep.
//  Barrier: one atomic arrival per block; thread 0 spins, block syncs.
//  Phase 2 (main): grid-stride quad mapping, identical math to best kernel:
//    lane lx owns y-row dy=lx; one LDG.256 per z covers the whole 128B tile
//    line per warp instruction (4 L1 wavefronts per point); depth-2 z pipe.
//  Reset: last departing block zeroes the barrier counters for next replay.
// ---------------------------------------------------------------------------
__global__ void __launch_bounds__(256) k_fused(const float* __restrict__ knots,
                                               const float* __restrict__ coords,
                                               float* __restrict__ out,
                                               int n, int nblocks)
{
    __shared__ uint2 srow[4][GSZ + 1];   // [dy][x] cell (2x half2), +1 pad

    // ---------------- Phase 1: prep ----------------
    for (int slab = blockIdx.x; slab < NSLAB; slab += nblocks) {
        int z  = slab >> 6;
        int y0 = slab & 63;
        int t  = threadIdx.x;
        {
            int dy = t >> 6;
            int x  = t & 63;
            int yr = min(y0, GSZ - 4) + dy;
            float4 k = __ldg(reinterpret_cast<const float4*>(knots)
                             + (z * GSZ + yr) * GSZ + x);
            __half2 h0 = __floats2half2_rn(k.x, k.y);
            __half2 h1 = __floats2half2_rn(k.z, k.w);
            uint2 cell;
            cell.x = *reinterpret_cast<unsigned*>(&h0);
            cell.y = *reinterpret_cast<unsigned*>(&h1);
            srow[dy][x] = cell;
        }
        __syncthreads();

        size_t base = (size_t)((z * GSZ + y0) * GSZ) * 8;
#pragma unroll
        for (int r = 0; r < 2; r++) {
            int o   = t + r * 256;
            int x0  = o >> 3;
            int j   = o & 7;
            int dyo = j >> 1;
            int q   = j & 1;
            int xr  = min(x0, GSZ - 4) + 2 * q;
            uint2 c0 = srow[dyo][xr];
            uint2 c1 = srow[dyo][xr + 1];
            g_tiles[base + o] = make_uint4(c0.x, c0.y, c1.x, c1.y);
        }
        __syncthreads();   // srow reused next slab
    }

    // ---------------- Barrier ----------------
    __threadfence();                  // publish tile writes (L2)
    __syncthreads();
    if (threadIdx.x == 0) {
        atomicAdd(&g_arrive, 1u);
        while (*((volatile unsigned*)&g_arrive) < (unsigned)nblocks) {
            __nanosleep(64);
        }
    }
    __syncthreads();
    __threadfence();                  // acquire ordering for tile reads

    // ---------------- Phase 2: main ----------------
    long long total = 4LL * n;
    long long stride = (long long)nblocks * 256;
    for (long long tid = (long long)blockIdx.x * 256 + threadIdx.x;
         tid < total; tid += stride) {
        int p  = (int)(tid >> 2);
        int lx = (int)(tid & 3);

        float zc = __ldg(&coords[p * 3 + 0]);
        float yc = __ldg(&coords[p * 3 + 1]);
        float xc = __ldg(&coords[p * 3 + 2]);

        float fz = floorf(zc), fy = floorf(yc), fx = floorf(xc);
        int iz = (int)fz, iy = (int)fy, ix = (int)fx;
        float sz = zc - fz, sy = yc - fy, sx = xc - fx;
        iz = min(max(iz, 1), GSZ - 3);
        iy = min(max(iy, 1), GSZ - 3);
        ix = min(max(ix, 1), GSZ - 3);

        const uint4* tbase = g_tiles
            + (size_t)(((iz - 1) * GSZ + (iy - 1)) * GSZ + (ix - 1)) * 8 + lx * 2;
        const size_t zstep = (size_t)(GSZ * GSZ * 8);

        unsigned A0, A1, A2, A3, A4, A5, A6, A7;
        unsigned B0, B1, B2, B3, B4, B5, B6, B7;
        LDG256(A, reinterpret_cast<const unsigned*>(tbase));
        LDG256(B, reinterpret_cast<const unsigned*>(tbase + zstep));

        float cz0 = sz * (-0.5f + sz * (1.0f - 0.5f * sz));
        float cz1 = 1.0f + sz * sz * (-2.5f + 1.5f * sz);
        float cz2 = sz * (0.5f + sz * (2.0f - 1.5f * sz));
        float cz3 = sz * sz * (0.5f * sz - 0.5f);

        float cyl;
        {
            float c0 = sy * (-0.5f + sy * (1.0f - 0.5f * sy));
            float c1 = 1.0f + sy * sy * (-2.5f + 1.5f * sy);
            float c2 = sy * (0.5f + sy * (2.0f - 1.5f * sy));
            float c3 = sy * sy * (0.5f * sy - 0.5f);
            float ca = (lx & 1) ? c1 : c0;
            float cb = (lx & 1) ? c3 : c2;
            cyl = (lx & 2) ? cb : ca;
        }

        __half2 hx0, hx1, hx2, hx3;
        {
            float c0 = sx * (-0.5f + sx * (1.0f - 0.5f * sx));
            float c1 = 1.0f + sx * sx * (-2.5f + 1.5f * sx);
            float c2 = sx * (0.5f + sx * (2.0f - 1.5f * sx));
            float c3 = sx * sx * (0.5f * sx - 0.5f);
            hx0 = __float2half2_rn(c0);
            hx1 = __float2half2_rn(c1);
            hx2 = __float2half2_rn(c2);
            hx3 = __float2half2_rn(c3);
        }

        float a0 = 0.f, a1 = 0.f, a2 = 0.f, a3 = 0.f;

        CONSUME(A, cz0 * cyl);
        LDG256(A, reinterpret_cast<const unsigned*>(tbase + 2 * zstep));
        CONSUME(B, cz1 * cyl);
        LDG256(B, reinterpret_cast<const unsigned*>(tbase + 3 * zstep));
        CONSUME(A, cz2 * cyl);
        CONSUME(B, cz3 * cyl);

#pragma unroll
        for (int d = 1; d < 4; d <<= 1) {
            a0 += __shfl_xor_sync(0xffffffffu, a0, d);
            a1 += __shfl_xor_sync(0xffffffffu, a1, d);
            a2 += __shfl_xor_sync(0xffffffffu, a2, d);
            a3 += __shfl_xor_sync(0xffffffffu, a3, d);
        }

        if (lx == 0)
            reinterpret_cast<float4*>(out)[p] = make_float4(a0, a1, a2, a3);
    }

    // ---------------- Reset for next replay ----------------
    __syncthreads();
    if (threadIdx.x == 0) {
        unsigned d = atomicAdd(&g_depart, 1u);
        if (d == (unsigned)(nblocks - 1)) {
            g_arrive = 0;
            g_depart = 0;
            __threadfence();
        }
    }
}

// ---------------------------------------------------------------------------
extern "C" void kernel_launch(void* const* d_in, const int* in_sizes, int n_in,
                              void* d_out, int out_size) {
    const float* coords = (const float*)d_in[0];  // [N,3] f32
    const float* knots  = (const float*)d_in[1];  // [64,64,64,4] f32
    float* out          = (float*)d_out;          // [N,4] f32

    int n = in_sizes[0] / 3;

    // Grid = exactly resident capacity (deadlock-safe for the spin barrier).
    int dev = 0, nsm = 0, per_sm = 0;
    cudaGetDevice(&dev);
    cudaDeviceGetAttribute(&nsm, cudaDevAttrMultiProcessorCount, dev);
    cudaError_t e = cudaOccupancyMaxActiveBlocksPerMultiprocessor(
        &per_sm, k_fused, 256, 0);
    if (e != cudaSuccess || per_sm < 1) per_sm = 1;   // conservative fallback
    if (nsm < 1) nsm = 1;
    int nblocks = nsm * per_sm;

    k_fused<<<nblocks, 256>>>(knots, coords, out, n, nblocks);
}